// round 7
// baseline (speedup 1.0000x reference)
#include <cuda_runtime.h>
#include <math.h>
#include <stdint.h>

#define MAXN 10000
#define MAXE 640000

// ---------------- device scratch ----------------
__device__ __align__(16) unsigned long long g_pk[MAXN];  // [wsum_fixed<<20 | cnt]
__device__ int g_done;
__device__ __align__(16) float g_dinv[MAXN];
__device__ __align__(16) float g_Xs[MAXN * 128];         // X * dinv (row-scaled)
__device__ __align__(16) int   g_off[MAXN + 1];
__device__ __align__(16) int   g_cursor[MAXN];
__device__ __align__(16) int2  g_csr[MAXE];              // (src, raw w)
__device__ __align__(16) float g_Y[MAXN * 128];
__device__ __align__(16) float g_Wall[256 * 512];        // permuted: [k][4j+g]
__device__ __align__(16) float g_ball[512];              // permuted: [4j+g]

__device__ __forceinline__ int clampi(int v, int n) {
    return v < 0 ? 0 : (v >= n ? n - 1 : v);
}
__device__ __forceinline__ uint32_t f2tf32(float f) {
    uint32_t r;
    asm("cvt.rna.tf32.f32 %0, %1;\n" : "=r"(r) : "f"(f));
    return r;
}
__device__ __forceinline__ float dinv_from_pk(unsigned long long pk) {
    float dg = 1.0f + (float)(pk >> 20) * (1.0f / 1048576.0f);
    return rsqrtf(fmaxf(dg, 1e-12f));
}

// ---------------- stage 1: init ----------------
__global__ void k_init(int N) {
    int n = blockIdx.x * blockDim.x + threadIdx.x;
    if (n < N) g_pk[n] = 0ull;
    if (n == 0) g_done = 0;
}

// ---------------- stage 2 (fused): degree atomics + scan + dinv + Xs ----------------
// All blocks: 64b packed atomic per edge. Trailing 65 blocks spin on a ticket,
// then block NB-1 does the CSR scan, blocks NB-65..NB-2 compute dinv + Xs.
#define WB 65
__global__ __launch_bounds__(256) void k_edgeF(const int* __restrict__ ei,
                                               const float* __restrict__ w,
                                               const float* __restrict__ X,
                                               int E, int N, int NB) {
    int b = blockIdx.x, t = threadIdx.x;
    int e = b * 256 + t;
    if (e < E) {
        int d = clampi(ei[E + e], N);
        unsigned int wf = __float2uint_rn(w[e] * 1048576.0f);
        atomicAdd(&g_pk[d], ((unsigned long long)wf << 20) | 1ull);
    }
    __threadfence();
    __syncthreads();
    if (t == 0) atomicAdd(&g_done, 1);

    if (b < NB - WB) return;

    if (t == 0) {
        while (atomicAdd(&g_done, 0) < NB) __nanosleep(128);
    }
    __syncthreads();

    if (b == NB - 1) {
        // ---- CSR scan (256 threads) ----
        __shared__ int ssum[8];
        int lane = t & 31, w5 = t >> 5;
        int chunk = (N + 255) / 256;
        int bgn = t * chunk, end = min(bgn + chunk, N);
        int s = 0;
        for (int i = bgn; i < end; i++) s += (int)(g_pk[i] & 0xFFFFFull);
        int incl = s;
        #pragma unroll
        for (int d = 1; d < 32; d <<= 1) {
            int v = __shfl_up_sync(0xffffffffu, incl, d);
            if (lane >= d) incl += v;
        }
        if (lane == 31) ssum[w5] = incl;
        __syncthreads();
        if (t == 0) {
            int run = 0;
            for (int i = 0; i < 8; i++) { int tmp = ssum[i]; ssum[i] = run; run += tmp; }
        }
        __syncthreads();
        int base = ssum[w5] + incl - s;
        for (int i = bgn; i < end; i++) {
            g_off[i] = base;
            g_cursor[i] = base;
            base += (int)(g_pk[i] & 0xFFFFFull);
        }
        if (t == 0) g_off[N] = E;
    } else {
        // ---- dinv + Xs (64 blocks x 256 threads) ----
        int wb = b - (NB - WB);                  // 0..63
        int id = wb * 256 + t;                   // 0..16383
        if (id < N) g_dinv[id] = dinv_from_pk(g_pk[id]);
        const float4* X4 = (const float4*)X;
        float4* Xs4 = (float4*)g_Xs;
        for (int i = id; i < N * 32; i += 64 * 256) {
            int row = i >> 5;
            float dv = dinv_from_pk(g_pk[row]);
            float4 x = X4[i];
            Xs4[i] = make_float4(x.x * dv, x.y * dv, x.z * dv, x.w * dv);
        }
    }
}

// ---------------- stage 3: CSR scatter (no dinv dependency on values) ----------------
__global__ void k_scatter(const int* __restrict__ ei,
                          const float* __restrict__ w, int E, int N) {
    int e = blockIdx.x * blockDim.x + threadIdx.x;
    if (e >= E) return;
    int s = clampi(ei[e], N);
    int d = clampi(ei[E + e], N);
    int pos = atomicAdd(&g_cursor[d], 1);
    if (pos < E) g_csr[pos] = make_int2(s, __float_as_int(w[e]));
}

// ---------------- stage 4: Y = A_norm @ X (warp per node, rows [n0,n1)) ----------------
__global__ void k_aggregate(int n0, int n1) {
    int warp = n0 + ((blockIdx.x * blockDim.x + threadIdx.x) >> 5);
    int lane = threadIdx.x & 31;
    if (warp >= n1) return;
    const float4* __restrict__ Xs4 = (const float4*)g_Xs;
    float di = g_dinv[warp];
    float4 acc = Xs4[warp * 32 + lane];          // self loop: dinv[d]*X[d]
    int s0 = g_off[warp], s1 = g_off[warp + 1];
    for (int e = s0; e < s1; e++) {
        int2 ed = __ldg(&g_csr[e]);
        float wv = __int_as_float(ed.y);
        float4 xs = Xs4[ed.x * 32 + lane];
        acc.x = fmaf(xs.x, wv, acc.x);
        acc.y = fmaf(xs.y, wv, acc.y);
        acc.z = fmaf(xs.z, wv, acc.z);
        acc.w = fmaf(xs.w, wv, acc.w);
    }
    acc.x *= di; acc.y *= di; acc.z *= di; acc.w *= di;
    ((float4*)g_Y)[warp * 32 + lane] = acc;
}

// ---------------- parallel branch: weight fold (gate-interleaved permute) ----------------
// blocks 0..63 : Wc_g @ Wl_g(top) tiles -> g_Wall[k][4j+g], k<128
// blocks 64..79: Wl bottom half copy   -> g_Wall[128+r][4j+g]
// block 80     : bias fold             -> g_ball[4j+g]
__global__ __launch_bounds__(1024) void k_weights(
    const float* __restrict__ Wc_i, const float* __restrict__ Wc_f,
    const float* __restrict__ Wc_o,
    const float* __restrict__ Wl_i, const float* __restrict__ Wl_f,
    const float* __restrict__ Wl_o, const float* __restrict__ Wl_ct,
    const float* __restrict__ bc_i, const float* __restrict__ bc_f,
    const float* __restrict__ bc_o,
    const float* __restrict__ bl_i, const float* __restrict__ bl_f,
    const float* __restrict__ bl_o, const float* __restrict__ bl_ct)
{
    __shared__ float As[32][128];
    __shared__ float Bs[128][32];
    int b = blockIdx.x, t = threadIdx.x;
    if (b < 64) {
        int g = b >> 4, tile = b & 15;
        int tr = tile >> 2, tc = tile & 3;
        // reference bug kept: ct gate reuses conv_f
        const float* Wc = (g == 0) ? Wc_i : (g == 2) ? Wc_o : Wc_f;
        const float* Wl = (g == 0) ? Wl_i : (g == 1) ? Wl_f : (g == 2) ? Wl_o : Wl_ct;
        #pragma unroll
        for (int it = 0; it < 4; it++) {
            int i = t + it * 1024;
            int r = i >> 7, k = i & 127;
            As[r][k] = Wc[(tr * 32 + r) * 128 + k];
        }
        #pragma unroll
        for (int it = 0; it < 4; it++) {
            int i = t + it * 1024;
            int k = i >> 5, c = i & 31;
            Bs[k][c] = Wl[k * 128 + tc * 32 + c];
        }
        __syncthreads();
        int r = t >> 5, c = t & 31;
        float acc = 0.f;
        #pragma unroll 16
        for (int k = 0; k < 128; k++) acc = fmaf(As[r][k], Bs[k][c], acc);
        g_Wall[(tr * 32 + r) * 512 + (tc * 32 + c) * 4 + g] = acc;
    } else if (b < 80) {
        int idx = (b - 64) * 1024 + t;           // 128 rows x 128 j
        int r2 = idx >> 7, j = idx & 127;
        int row = 128 + r2;
        g_Wall[row * 512 + j * 4 + 0] = Wl_i[row * 128 + j];
        g_Wall[row * 512 + j * 4 + 1] = Wl_f[row * 128 + j];
        g_Wall[row * 512 + j * 4 + 2] = Wl_o[row * 128 + j];
        g_Wall[row * 512 + j * 4 + 3] = Wl_ct[row * 128 + j];
    } else {
        if (t < 512) {
            int j = t >> 2, g = t & 3;
            const float* Wl = (g == 0) ? Wl_i : (g == 1) ? Wl_f : (g == 2) ? Wl_o : Wl_ct;
            const float* bc = (g == 0) ? bc_i : (g == 2) ? bc_o : bc_f;
            const float* bl = (g == 0) ? bl_i : (g == 1) ? bl_f : (g == 2) ? bl_o : bl_ct;
            float s = bl[j];
            #pragma unroll 16
            for (int k = 0; k < 128; k++) s = fmaf(bc[k], Wl[k * 128 + j], s);
            g_ball[t] = s;
        }
    }
}

// ---------------- stage 5: tf32 GEMM + fused LSTM epilogue ----------------
// pre[N,512(perm)] = [Y|H] @ g_Wall + g_ball; epilogue in registers via lane-pair shfl
#define GM 64
#define GN 128
#define GK 32
#define AS_STRIDE 72    // (GM+8): qid*72%32=qid*8 -> conflict-free frag loads
#define BS_STRIDE 136   // (GN+8)

__global__ __launch_bounds__(256) void k_gemm_ep(const float* __restrict__ H,
                                                 const float* __restrict__ C,
                                                 float* __restrict__ out,
                                                 int N, int yOff) {
    __shared__ uint32_t As[GK * AS_STRIDE];
    __shared__ uint32_t Bs[GK * BS_STRIDE];

    int tid = threadIdx.x;
    int wid = tid >> 5;
    int lane = tid & 31;
    int warpM = wid & 1;           // 2 warps M
    int warpN = wid >> 1;          // 4 warps N
    int rowBase = (blockIdx.y + yOff) * GM;
    int colBase = blockIdx.x * GN;
    int grp = lane >> 2;
    int qid = lane & 3;

    float4 aReg[2];
    float4 bReg[4];

    #define LOAD_A_REG(k0)                                                        \
        {                                                                         \
            const float* _src = ((k0) < 128) ? g_Y : H;                           \
            int _koff = ((k0) < 128) ? (k0) : (k0) - 128;                         \
            _Pragma("unroll")                                                     \
            for (int it = 0; it < 2; it++) {                                      \
                int i = tid + it * 256;                                           \
                int r = i >> 3, c4 = i & 7;                                       \
                int gr = rowBase + r;                                             \
                aReg[it] = (gr < N)                                               \
                    ? *(const float4*)&_src[gr * 128 + _koff + c4 * 4]            \
                    : make_float4(0.f, 0.f, 0.f, 0.f);                            \
            }                                                                     \
        }
    #define LOAD_B_REG(k0)                                                        \
        {                                                                         \
            _Pragma("unroll")                                                     \
            for (int it = 0; it < 4; it++) {                                      \
                int i = tid + it * 256;                                           \
                int r = i >> 5, c4 = i & 31;                                      \
                bReg[it] = *(const float4*)&g_Wall[((k0) + r) * 512 + colBase + c4 * 4]; \
            }                                                                     \
        }
    #define STORE_TILES()                                                         \
        {                                                                         \
            _Pragma("unroll")                                                     \
            for (int it = 0; it < 2; it++) {                                      \
                int i = tid + it * 256;                                           \
                int r = i >> 3, c4 = i & 7;                                       \
                As[(c4 * 4 + 0) * AS_STRIDE + r] = f2tf32(aReg[it].x);            \
                As[(c4 * 4 + 1) * AS_STRIDE + r] = f2tf32(aReg[it].y);            \
                As[(c4 * 4 + 2) * AS_STRIDE + r] = f2tf32(aReg[it].z);            \
                As[(c4 * 4 + 3) * AS_STRIDE + r] = f2tf32(aReg[it].w);            \
            }                                                                     \
            _Pragma("unroll")                                                     \
            for (int it = 0; it < 4; it++) {                                      \
                int i = tid + it * 256;                                           \
                int r = i >> 5, c4 = i & 31;                                      \
                Bs[r * BS_STRIDE + c4 * 4 + 0] = f2tf32(bReg[it].x);              \
                Bs[r * BS_STRIDE + c4 * 4 + 1] = f2tf32(bReg[it].y);              \
                Bs[r * BS_STRIDE + c4 * 4 + 2] = f2tf32(bReg[it].z);              \
                Bs[r * BS_STRIDE + c4 * 4 + 3] = f2tf32(bReg[it].w);              \
            }                                                                     \
        }

    float acc[2][4][4];
    #pragma unroll
    for (int i = 0; i < 2; i++)
        #pragma unroll
        for (int j = 0; j < 4; j++)
            #pragma unroll
            for (int t2 = 0; t2 < 4; t2++) acc[i][j][t2] = 0.f;

    LOAD_A_REG(0); LOAD_B_REG(0);
    STORE_TILES();
    __syncthreads();

    for (int k0 = 0; k0 < 256; k0 += GK) {
        int kn = k0 + GK;
        if (kn < 256) { LOAD_A_REG(kn); LOAD_B_REG(kn); }

        #pragma unroll
        for (int kk = 0; kk < GK; kk += 8) {
            uint32_t a[2][4];
            #pragma unroll
            for (int mf = 0; mf < 2; mf++) {
                int row0 = warpM * 32 + mf * 16;
                a[mf][0] = As[(kk + qid) * AS_STRIDE + row0 + grp];
                a[mf][1] = As[(kk + qid) * AS_STRIDE + row0 + 8 + grp];
                a[mf][2] = As[(kk + 4 + qid) * AS_STRIDE + row0 + grp];
                a[mf][3] = As[(kk + 4 + qid) * AS_STRIDE + row0 + 8 + grp];
            }
            uint32_t bf[4][2];
            #pragma unroll
            for (int nf = 0; nf < 4; nf++) {
                int col0 = warpN * 32 + nf * 8;
                bf[nf][0] = Bs[(kk + qid) * BS_STRIDE + col0 + grp];
                bf[nf][1] = Bs[(kk + 4 + qid) * BS_STRIDE + col0 + grp];
            }
            #pragma unroll
            for (int mf = 0; mf < 2; mf++)
                #pragma unroll
                for (int nf = 0; nf < 4; nf++) {
                    asm volatile(
                        "mma.sync.aligned.m16n8k8.row.col.f32.tf32.tf32.f32 "
                        "{%0,%1,%2,%3}, {%4,%5,%6,%7}, {%8,%9}, {%0,%1,%2,%3};\n"
                        : "+f"(acc[mf][nf][0]), "+f"(acc[mf][nf][1]),
                          "+f"(acc[mf][nf][2]), "+f"(acc[mf][nf][3])
                        : "r"(a[mf][0]), "r"(a[mf][1]), "r"(a[mf][2]), "r"(a[mf][3]),
                          "r"(bf[nf][0]), "r"(bf[nf][1]));
                }
        }
        __syncthreads();
        if (kn < 256) {
            STORE_TILES();
            __syncthreads();
        }
    }

    // ---- fused epilogue ----
    // col n = colBase + warpN*32 + nf*8 + qid*2. gate = n&3 (even qid: i,f; odd: o,ct),
    // j = n>>2 shared by the qid-parity lane pair. Exchange via shfl_xor(1).
    bool ev = (qid & 1) == 0;
    #pragma unroll
    for (int mf = 0; mf < 2; mf++) {
        int rEven = rowBase + warpM * 32 + mf * 16 + grp;
        #pragma unroll
        for (int nf = 0; nf < 4; nf++) {
            int n = colBase + warpN * 32 + nf * 8 + qid * 2;
            float c0 = acc[mf][nf][0] + g_ball[n];
            float c1 = acc[mf][nf][1] + g_ball[n + 1];
            float c2 = acc[mf][nf][2] + g_ball[n];
            float c3 = acc[mf][nf][3] + g_ball[n + 1];
            float sA = ev ? c2 : c0;
            float sB = ev ? c3 : c1;
            float rA = __shfl_xor_sync(0xffffffffu, sA, 1);
            float rB = __shfl_xor_sync(0xffffffffu, sB, 1);
            int row = ev ? rEven : rEven + 8;
            float gi = ev ? c0 : rA;
            float gf = ev ? c1 : rB;
            float go = ev ? rA : c2;
            float gct = ev ? rB : c3;
            int j = n >> 2;
            if (row < N) {
                float I  = 1.f / (1.f + __expf(-gi));
                float Fg = 1.f / (1.f + __expf(-gf));
                float O  = 1.f / (1.f + __expf(-go));
                float Ct = tanhf(gct);
                float Cn = Ct * I + Fg * C[row * 128 + j];
                float Hn = O * tanhf(Cn);
                out[row * 128 + j] = Hn;
                out[N * 128 + row * 128 + j] = Cn;
            }
        }
    }
}

// ---------------- launch ----------------
extern "C" void kernel_launch(void* const* d_in, const int* in_sizes, int n_in,
                              void* d_out, int out_size) {
    const float* X  = (const float*)d_in[0];
    const int*   ei = (const int*)d_in[1];      // int32 (JAX x64 disabled)
    const float* ew = (const float*)d_in[2];
    const float* H  = (const float*)d_in[3];
    const float* C  = (const float*)d_in[4];
    const float *Wc_i = (const float*)d_in[5],  *bc_i = (const float*)d_in[6],
                *Wl_i = (const float*)d_in[7],  *bl_i = (const float*)d_in[8];
    const float *Wc_f = (const float*)d_in[9],  *bc_f = (const float*)d_in[10],
                *Wl_f = (const float*)d_in[11], *bl_f = (const float*)d_in[12];
    const float *Wc_o = (const float*)d_in[13], *bc_o = (const float*)d_in[14],
                *Wl_o = (const float*)d_in[15], *bl_o = (const float*)d_in[16];
    const float *Wl_ct = (const float*)d_in[19], *bl_ct = (const float*)d_in[20];

    int N = in_sizes[0] / 128;
    int E = in_sizes[2];
    float* out = (float*)d_out;

    cudaStream_t s2;
    cudaStreamCreateWithFlags(&s2, cudaStreamNonBlocking);
    cudaEvent_t evFork, evA, evB, evJoin;
    cudaEventCreateWithFlags(&evFork, cudaEventDisableTiming);
    cudaEventCreateWithFlags(&evA, cudaEventDisableTiming);
    cudaEventCreateWithFlags(&evB, cudaEventDisableTiming);
    cudaEventCreateWithFlags(&evJoin, cudaEventDisableTiming);

    // fork: weight fold (inputs only)
    cudaEventRecord(evFork, 0);
    cudaStreamWaitEvent(s2, evFork, 0);
    k_weights<<<81, 1024, 0, s2>>>(Wc_i, Wc_f, Wc_o,
                                   Wl_i, Wl_f, Wl_o, Wl_ct,
                                   bc_i, bc_f, bc_o,
                                   bl_i, bl_f, bl_o, bl_ct);

    // main chain
    int NB = (E + 255) / 256;
    k_init<<<(N + 255) / 256, 256>>>(N);
    k_edgeF<<<NB, 256>>>(ei, ew, X, E, N, NB);
    k_scatter<<<NB, 256>>>(ei, ew, E, N);

    int nmid = 4992;                              // 78 * 64
    if (nmid > N) nmid = N;
    k_aggregate<<<(nmid * 32 + 255) / 256, 256>>>(0, nmid);
    cudaEventRecord(evA, 0);
    if (N > nmid)
        k_aggregate<<<((N - nmid) * 32 + 255) / 256, 256>>>(nmid, N);
    cudaEventRecord(evB, 0);

    // gemm halves on s2 (after weights, pipelined against aggregate)
    int yLo = nmid / GM;                          // 78
    int yHi = (N + GM - 1) / GM - yLo;            // 79
    cudaStreamWaitEvent(s2, evA, 0);
    k_gemm_ep<<<dim3(512 / GN, yLo), 256, 0, s2>>>(H, C, out, N, 0);
    cudaStreamWaitEvent(s2, evB, 0);
    if (yHi > 0)
        k_gemm_ep<<<dim3(512 / GN, yHi), 256, 0, s2>>>(H, C, out, N, yLo);
    cudaEventRecord(evJoin, s2);
    cudaStreamWaitEvent(0, evJoin, 0);
}

// round 8
// speedup vs baseline: 1.2347x; 1.2347x over previous
#include <cuda_runtime.h>
#include <math.h>
#include <stdint.h>

#define MAXN 10000
#define MAXE 640000

// ---------------- device scratch ----------------
__device__ __align__(16) unsigned long long g_pk[MAXN];  // [wsum_fixed<<20 | cnt]
__device__ __align__(16) float g_dinv[MAXN];
__device__ __align__(16) int   g_off[MAXN + 1];
__device__ __align__(16) int   g_cursor[MAXN];
__device__ __align__(16) int2  g_csr[MAXE];              // (src, w*dinv[src])
__device__ __align__(16) float g_Y[MAXN * 128];
__device__ __align__(16) float g_Wall[256 * 512];        // permuted: [k][4j+g]
__device__ __align__(16) float g_ball[512];              // permuted: [4j+g]

__device__ __forceinline__ int clampi(int v, int n) {
    return v < 0 ? 0 : (v >= n ? n - 1 : v);
}
__device__ __forceinline__ uint32_t f2tf32(float f) {
    uint32_t r;
    asm("cvt.rna.tf32.f32 %0, %1;\n" : "=r"(r) : "f"(f));
    return r;
}

// ---------------- stage 1: init ----------------
__global__ void k_init(int N) {
    int n = blockIdx.x * blockDim.x + threadIdx.x;
    if (n < N) g_pk[n] = 0ull;
}

// ---------------- stage 2: packed degree+count (one 64b atomic per edge) ----------------
__global__ void k_edge_deg(const int* __restrict__ ei,
                           const float* __restrict__ w, int E, int N) {
    int e = blockIdx.x * blockDim.x + threadIdx.x;
    if (e >= E) return;
    int d = clampi(ei[E + e], N);
    unsigned int wf = __float2uint_rn(w[e] * 1048576.0f);   // 2^20 fixed point
    atomicAdd(&g_pk[d], ((unsigned long long)wf << 20) | 1ull);
}

// ---------------- stage 3a: scan + dinv (11 blocks) ----------------
__global__ __launch_bounds__(1024) void k_midA(int N, int E) {
    __shared__ int wsum[32];
    int b = blockIdx.x, t = threadIdx.x;
    if (b == 0) {
        int lane = t & 31, w5 = t >> 5;
        int chunk = (N + 1023) >> 10;                  // <=16
        int bgn = t * chunk;
        int end = min(bgn + chunk, N);
        int m = end > bgn ? end - bgn : 0;
        int cnt[16];
        int s = 0;
        #pragma unroll
        for (int i = 0; i < 16; i++) {
            if (i < m) { cnt[i] = (int)(g_pk[bgn + i] & 0xFFFFFull); s += cnt[i]; }
        }
        int incl = s;
        #pragma unroll
        for (int d = 1; d < 32; d <<= 1) {
            int v = __shfl_up_sync(0xffffffffu, incl, d);
            if (lane >= d) incl += v;
        }
        if (lane == 31) wsum[w5] = incl;
        __syncthreads();
        if (w5 == 0) {
            int v = wsum[lane];
            int iv = v;
            #pragma unroll
            for (int d = 1; d < 32; d <<= 1) {
                int u = __shfl_up_sync(0xffffffffu, iv, d);
                if (lane >= d) iv += u;
            }
            wsum[lane] = iv - v;
        }
        __syncthreads();
        int base = wsum[w5] + (incl - s);
        #pragma unroll
        for (int i = 0; i < 16; i++) {
            if (i < m) {
                g_off[bgn + i] = base;
                g_cursor[bgn + i] = base;
                base += cnt[i];
            }
        }
        if (t == 0) g_off[N] = E;
    } else {
        int n = (b - 1) * 1024 + t;
        if (n < N) {
            unsigned long long pk = g_pk[n];
            float dg = 1.0f + (float)((double)(pk >> 20) * (1.0 / 1048576.0));
            g_dinv[n] = dg > 0.f ? rsqrtf(fmaxf(dg, 1e-12f)) : 0.f;
        }
    }
}

// ---------------- stage 3b (parallel branch): weight fold, gate-interleaved ----------------
// blocks 0..63 : Wc_g @ Wl_g(top) tiles -> g_Wall[k][4j+g], k<128
// blocks 64..79: Wl bottom half copy   -> g_Wall[128+r][4j+g]
// block 80     : bias fold             -> g_ball[4j+g]
__global__ __launch_bounds__(1024) void k_weights(
    const float* __restrict__ Wc_i, const float* __restrict__ Wc_f,
    const float* __restrict__ Wc_o,
    const float* __restrict__ Wl_i, const float* __restrict__ Wl_f,
    const float* __restrict__ Wl_o, const float* __restrict__ Wl_ct,
    const float* __restrict__ bc_i, const float* __restrict__ bc_f,
    const float* __restrict__ bc_o,
    const float* __restrict__ bl_i, const float* __restrict__ bl_f,
    const float* __restrict__ bl_o, const float* __restrict__ bl_ct)
{
    __shared__ float As[32][128];
    __shared__ float Bs[128][32];
    int b = blockIdx.x, t = threadIdx.x;
    if (b < 64) {
        int g = b >> 4, tile = b & 15;
        int tr = tile >> 2, tc = tile & 3;
        // reference bug kept: ct gate reuses conv_f
        const float* Wc = (g == 0) ? Wc_i : (g == 2) ? Wc_o : Wc_f;
        const float* Wl = (g == 0) ? Wl_i : (g == 1) ? Wl_f : (g == 2) ? Wl_o : Wl_ct;
        #pragma unroll
        for (int it = 0; it < 4; it++) {
            int i = t + it * 1024;
            int r = i >> 7, k = i & 127;
            As[r][k] = Wc[(tr * 32 + r) * 128 + k];
        }
        #pragma unroll
        for (int it = 0; it < 4; it++) {
            int i = t + it * 1024;
            int k = i >> 5, c = i & 31;
            Bs[k][c] = Wl[k * 128 + tc * 32 + c];
        }
        __syncthreads();
        int r = t >> 5, c = t & 31;
        float acc = 0.f;
        #pragma unroll 16
        for (int k = 0; k < 128; k++) acc = fmaf(As[r][k], Bs[k][c], acc);
        g_Wall[(tr * 32 + r) * 512 + (tc * 32 + c) * 4 + g] = acc;
    } else if (b < 80) {
        int idx = (b - 64) * 1024 + t;           // 128 rows x 128 j
        int r2 = idx >> 7, j = idx & 127;
        int row = 128 + r2;
        g_Wall[row * 512 + j * 4 + 0] = Wl_i[row * 128 + j];
        g_Wall[row * 512 + j * 4 + 1] = Wl_f[row * 128 + j];
        g_Wall[row * 512 + j * 4 + 2] = Wl_o[row * 128 + j];
        g_Wall[row * 512 + j * 4 + 3] = Wl_ct[row * 128 + j];
    } else {
        if (t < 512) {
            int j = t >> 2, g = t & 3;
            const float* Wl = (g == 0) ? Wl_i : (g == 1) ? Wl_f : (g == 2) ? Wl_o : Wl_ct;
            const float* bc = (g == 0) ? bc_i : (g == 2) ? bc_o : bc_f;
            const float* bl = (g == 0) ? bl_i : (g == 1) ? bl_f : (g == 2) ? bl_o : bl_ct;
            float s = bl[j];
            #pragma unroll 16
            for (int k = 0; k < 128; k++) s = fmaf(bc[k], Wl[k * 128 + j], s);
            g_ball[t] = s;
        }
    }
}

// ---------------- stage 4: CSR scatter (packed 8B store) ----------------
__global__ void k_scatter(const int* __restrict__ ei,
                          const float* __restrict__ w, int E, int N) {
    int e = blockIdx.x * blockDim.x + threadIdx.x;
    if (e >= E) return;
    int s = clampi(ei[e], N);
    int d = clampi(ei[E + e], N);
    int pos = atomicAdd(&g_cursor[d], 1);
    if (pos < E) {
        float nrm = w[e] * g_dinv[s];                  // dinv[d] applied in aggregate
        g_csr[pos] = make_int2(s, __float_as_int(nrm));
    }
}

// ---------------- stage 5: Y = A_norm @ X (warp per node) ----------------
__global__ void k_aggregate(const float* __restrict__ X, int N) {
    int warp = (blockIdx.x * blockDim.x + threadIdx.x) >> 5;
    int lane = threadIdx.x & 31;
    if (warp >= N) return;
    const float4* __restrict__ X4 = (const float4*)X;
    float di = g_dinv[warp];
    float4 x = X4[warp * 32 + lane];
    float4 acc = make_float4(x.x * di, x.y * di, x.z * di, x.w * di);
    int s0 = g_off[warp], s1 = g_off[warp + 1];
    for (int e = s0; e < s1; e++) {
        int2 ed = __ldg(&g_csr[e]);
        float wv = __int_as_float(ed.y);
        float4 xs = X4[ed.x * 32 + lane];
        acc.x = fmaf(xs.x, wv, acc.x);
        acc.y = fmaf(xs.y, wv, acc.y);
        acc.z = fmaf(xs.z, wv, acc.z);
        acc.w = fmaf(xs.w, wv, acc.w);
    }
    acc.x *= di; acc.y *= di; acc.z *= di; acc.w *= di;
    ((float4*)g_Y)[warp * 32 + lane] = acc;
}

// ---------------- stage 6: tf32 GEMM + fused LSTM epilogue (coalesced) ----------------
#define GM 64
#define GN 128
#define GK 32
#define AS_STRIDE 72
#define BS_STRIDE 136
#define SMEM_WORDS (GK * AS_STRIDE + GK * BS_STRIDE)   // 6656 words = 26 KB
#define EP_STRIDE 36                                    // 64 x 36 floats per H/C tile

__global__ __launch_bounds__(256) void k_gemm_ep(const float* __restrict__ H,
                                                 const float* __restrict__ C,
                                                 float* __restrict__ out, int N) {
    __shared__ uint32_t smemBuf[SMEM_WORDS];
    uint32_t* As = smemBuf;
    uint32_t* Bs = smemBuf + GK * AS_STRIDE;

    int tid = threadIdx.x;
    int wid = tid >> 5;
    int lane = tid & 31;
    int warpM = wid & 1;           // 2 warps M
    int warpN = wid >> 1;          // 4 warps N
    int rowBase = blockIdx.y * GM;
    int colBase = blockIdx.x * GN;
    int grp = lane >> 2;
    int qid = lane & 3;

    float4 aReg[2];
    float4 bReg[4];

    #define LOAD_A_REG(k0)                                                        \
        {                                                                         \
            const float* _src = ((k0) < 128) ? g_Y : H;                           \
            int _koff = ((k0) < 128) ? (k0) : (k0) - 128;                         \
            _Pragma("unroll")                                                     \
            for (int it = 0; it < 2; it++) {                                      \
                int i = tid + it * 256;                                           \
                int r = i >> 3, c4 = i & 7;                                       \
                int gr = rowBase + r;                                             \
                aReg[it] = (gr < N)                                               \
                    ? *(const float4*)&_src[gr * 128 + _koff + c4 * 4]            \
                    : make_float4(0.f, 0.f, 0.f, 0.f);                            \
            }                                                                     \
        }
    #define LOAD_B_REG(k0)                                                        \
        {                                                                         \
            _Pragma("unroll")                                                     \
            for (int it = 0; it < 4; it++) {                                      \
                int i = tid + it * 256;                                           \
                int r = i >> 5, c4 = i & 31;                                      \
                bReg[it] = *(const float4*)&g_Wall[((k0) + r) * 512 + colBase + c4 * 4]; \
            }                                                                     \
        }
    #define STORE_TILES()                                                         \
        {                                                                         \
            _Pragma("unroll")                                                     \
            for (int it = 0; it < 2; it++) {                                      \
                int i = tid + it * 256;                                           \
                int r = i >> 3, c4 = i & 7;                                       \
                As[(c4 * 4 + 0) * AS_STRIDE + r] = f2tf32(aReg[it].x);            \
                As[(c4 * 4 + 1) * AS_STRIDE + r] = f2tf32(aReg[it].y);            \
                As[(c4 * 4 + 2) * AS_STRIDE + r] = f2tf32(aReg[it].z);            \
                As[(c4 * 4 + 3) * AS_STRIDE + r] = f2tf32(aReg[it].w);            \
            }                                                                     \
            _Pragma("unroll")                                                     \
            for (int it = 0; it < 4; it++) {                                      \
                int i = tid + it * 256;                                           \
                int r = i >> 5, c4 = i & 31;                                      \
                Bs[r * BS_STRIDE + c4 * 4 + 0] = f2tf32(bReg[it].x);              \
                Bs[r * BS_STRIDE + c4 * 4 + 1] = f2tf32(bReg[it].y);              \
                Bs[r * BS_STRIDE + c4 * 4 + 2] = f2tf32(bReg[it].z);              \
                Bs[r * BS_STRIDE + c4 * 4 + 3] = f2tf32(bReg[it].w);              \
            }                                                                     \
        }

    float acc[2][4][4];
    #pragma unroll
    for (int i = 0; i < 2; i++)
        #pragma unroll
        for (int j = 0; j < 4; j++)
            #pragma unroll
            for (int t2 = 0; t2 < 4; t2++) acc[i][j][t2] = 0.f;

    LOAD_A_REG(0); LOAD_B_REG(0);
    STORE_TILES();
    __syncthreads();

    for (int k0 = 0; k0 < 256; k0 += GK) {
        int kn = k0 + GK;
        if (kn < 256) { LOAD_A_REG(kn); LOAD_B_REG(kn); }

        #pragma unroll
        for (int kk = 0; kk < GK; kk += 8) {
            uint32_t a[2][4];
            #pragma unroll
            for (int mf = 0; mf < 2; mf++) {
                int row0 = warpM * 32 + mf * 16;
                a[mf][0] = As[(kk + qid) * AS_STRIDE + row0 + grp];
                a[mf][1] = As[(kk + qid) * AS_STRIDE + row0 + 8 + grp];
                a[mf][2] = As[(kk + 4 + qid) * AS_STRIDE + row0 + grp];
                a[mf][3] = As[(kk + 4 + qid) * AS_STRIDE + row0 + 8 + grp];
            }
            uint32_t bf[4][2];
            #pragma unroll
            for (int nf = 0; nf < 4; nf++) {
                int col0 = warpN * 32 + nf * 8;
                bf[nf][0] = Bs[(kk + qid) * BS_STRIDE + col0 + grp];
                bf[nf][1] = Bs[(kk + 4 + qid) * BS_STRIDE + col0 + grp];
            }
            #pragma unroll
            for (int mf = 0; mf < 2; mf++)
                #pragma unroll
                for (int nf = 0; nf < 4; nf++) {
                    asm volatile(
                        "mma.sync.aligned.m16n8k8.row.col.f32.tf32.tf32.f32 "
                        "{%0,%1,%2,%3}, {%4,%5,%6,%7}, {%8,%9}, {%0,%1,%2,%3};\n"
                        : "+f"(acc[mf][nf][0]), "+f"(acc[mf][nf][1]),
                          "+f"(acc[mf][nf][2]), "+f"(acc[mf][nf][3])
                        : "r"(a[mf][0]), "r"(a[mf][1]), "r"(a[mf][2]), "r"(a[mf][3]),
                          "r"(bf[nf][0]), "r"(bf[nf][1]));
                }
        }
        __syncthreads();
        if (kn < 256) {
            STORE_TILES();
            __syncthreads();
        }
    }

    // ---- fused epilogue: gates in registers (lane-pair shfl), stage H/C in smem ----
    __syncthreads();   // all warps done reading As/Bs before overwrite
    float* SH = (float*)smemBuf;                       // [64][EP_STRIDE]
    float* SC = (float*)smemBuf + GM * EP_STRIDE;      // [64][EP_STRIDE]

    bool evn = (qid & 1) == 0;
    #pragma unroll
    for (int mf = 0; mf < 2; mf++) {
        int rEvenL = warpM * 32 + mf * 16 + grp;       // local row (even-qid lane)
        #pragma unroll
        for (int nf = 0; nf < 4; nf++) {
            int n = colBase + warpN * 32 + nf * 8 + qid * 2;
            float c0 = acc[mf][nf][0] + g_ball[n & 511];
            float c1 = acc[mf][nf][1] + g_ball[(n + 1) & 511];
            float c2 = acc[mf][nf][2] + g_ball[n & 511];
            float c3 = acc[mf][nf][3] + g_ball[(n + 1) & 511];
            float sA = evn ? c2 : c0;
            float sB = evn ? c3 : c1;
            float rA = __shfl_xor_sync(0xffffffffu, sA, 1);
            float rB = __shfl_xor_sync(0xffffffffu, sB, 1);
            int rowL = evn ? rEvenL : rEvenL + 8;
            float gi  = evn ? c0 : rA;
            float gf  = evn ? c1 : rB;
            float go  = evn ? rA : c2;
            float gct = evn ? rB : c3;
            int j = n >> 2;
            int jL = j - (colBase >> 2);               // 0..31
            int row = rowBase + rowL;
            float I  = 1.f / (1.f + __expf(-gi));
            float Fg = 1.f / (1.f + __expf(-gf));
            float O  = 1.f / (1.f + __expf(-go));
            float Ct = tanhf(gct);
            float Cprev = (row < N) ? C[row * 128 + j] : 0.f;
            float Cn = Ct * I + Fg * Cprev;
            float Hn = O * tanhf(Cn);
            SH[rowL * EP_STRIDE + jL] = Hn;
            SC[rowL * EP_STRIDE + jL] = Cn;
        }
    }
    __syncthreads();

    // coalesced write-out: 64 rows x 32 cols per tile, float4
    int colOff = colBase >> 2;                         // 32-col window
    #pragma unroll
    for (int it = 0; it < 2; it++) {
        int i = tid + it * 256;                        // 0..511
        int r = i >> 3, c4 = i & 7;
        int row = rowBase + r;
        if (row < N) {
            float4 h = *(float4*)&SH[r * EP_STRIDE + c4 * 4];
            float4 c = *(float4*)&SC[r * EP_STRIDE + c4 * 4];
            *(float4*)&out[row * 128 + colOff + c4 * 4] = h;
            *(float4*)&out[N * 128 + row * 128 + colOff + c4 * 4] = c;
        }
    }
}

// ---------------- launch ----------------
extern "C" void kernel_launch(void* const* d_in, const int* in_sizes, int n_in,
                              void* d_out, int out_size) {
    const float* X  = (const float*)d_in[0];
    const int*   ei = (const int*)d_in[1];      // int32 (JAX x64 disabled)
    const float* ew = (const float*)d_in[2];
    const float* H  = (const float*)d_in[3];
    const float* C  = (const float*)d_in[4];
    const float *Wc_i = (const float*)d_in[5],  *bc_i = (const float*)d_in[6],
                *Wl_i = (const float*)d_in[7],  *bl_i = (const float*)d_in[8];
    const float *Wc_f = (const float*)d_in[9],  *bc_f = (const float*)d_in[10],
                *Wl_f = (const float*)d_in[11], *bl_f = (const float*)d_in[12];
    const float *Wc_o = (const float*)d_in[13], *bc_o = (const float*)d_in[14],
                *Wl_o = (const float*)d_in[15], *bl_o = (const float*)d_in[16];
    const float *Wl_ct = (const float*)d_in[19], *bl_ct = (const float*)d_in[20];

    int N = in_sizes[0] / 128;
    int E = in_sizes[2];
    float* out = (float*)d_out;

    cudaStream_t s2;
    cudaStreamCreateWithFlags(&s2, cudaStreamNonBlocking);
    cudaEvent_t evFork, evJoin;
    cudaEventCreateWithFlags(&evFork, cudaEventDisableTiming);
    cudaEventCreateWithFlags(&evJoin, cudaEventDisableTiming);

    // fork: weight fold (inputs only)
    cudaEventRecord(evFork, 0);
    cudaStreamWaitEvent(s2, evFork, 0);
    k_weights<<<81, 1024, 0, s2>>>(Wc_i, Wc_f, Wc_o,
                                   Wl_i, Wl_f, Wl_o, Wl_ct,
                                   bc_i, bc_f, bc_o,
                                   bl_i, bl_f, bl_o, bl_ct);
    cudaEventRecord(evJoin, s2);

    // main chain
    k_init<<<(N + 255) / 256, 256>>>(N);
    k_edge_deg<<<(E + 255) / 256, 256>>>(ei, ew, E, N);
    k_midA<<<11, 1024>>>(N, E);
    k_scatter<<<(E + 255) / 256, 256>>>(ei, ew, E, N);
    k_aggregate<<<(N * 32 + 255) / 256, 256>>>(X, N);

    // join before fused GEMM+epilogue
    cudaStreamWaitEvent(0, evJoin, 0);
    k_gemm_ep<<<dim3(512 / GN, (N + GM - 1) / GM), 256>>>(H, C, out, N);
}